// round 7
// baseline (speedup 1.0000x reference)
#include <cuda_runtime.h>

#define BATCH 2
#define NPTS  4096
#define NTOT  (BATCH*NPTS)
#define HALF_J 2048

#define LOG2E_F 1.4426950408889634f
#define LN2_F   0.6931471805599453f
#define LOGW_F  (-8.317766166719343f)   /* -ln(4096), uniform weights both sides */

// Packed point data: (x, y, z, 0.5*|p|^2)
__device__ float4 g_PX[NTOT];   // true_data  (x side)
__device__ float4 g_PY[NTOT];   // particles  (y side)
// Dual potentials, double-buffered: [buffer][which][B*N]
// which: 0 = a_y, 1 = b_x, 2 = a_x, 3 = b_y
__device__ float  g_dual[2][4][NTOT];

// ---- f32x2 packed helpers (sm_103a) ----
__device__ __forceinline__ unsigned long long pack2(float lo, float hi){
    unsigned long long r;
    asm("mov.b64 %0, {%1, %2};" : "=l"(r)
        : "r"(__float_as_uint(lo)), "r"(__float_as_uint(hi)));
    return r;
}
__device__ __forceinline__ void unpack2(unsigned long long v, float &lo, float &hi){
    unsigned int a, b;
    asm("mov.b64 {%0, %1}, %2;" : "=r"(a), "=r"(b) : "l"(v));
    lo = __uint_as_float(a); hi = __uint_as_float(b);
}
__device__ __forceinline__ unsigned long long ffma2(unsigned long long a,
                                                    unsigned long long b,
                                                    unsigned long long c){
    unsigned long long d;
    asm("fma.rn.f32x2 %0, %1, %2, %3;" : "=l"(d) : "l"(a), "l"(b), "l"(c));
    return d;
}
__device__ __forceinline__ unsigned long long fadd2(unsigned long long a,
                                                    unsigned long long b){
    unsigned long long d;
    asm("add.rn.f32x2 %0, %1, %2;" : "=l"(d) : "l"(a), "l"(b));
    return d;
}
__device__ __forceinline__ float ex2f(float x){ float r; asm("ex2.approx.ftz.f32 %0, %1;" : "=f"(r) : "f"(x)); return r; }
__device__ __forceinline__ float lg2f(float x){ float r; asm("lg2.approx.f32 %0, %1;"     : "=f"(r) : "f"(x)); return r; }

__global__ void pack_kernel(const float* __restrict__ x, const float* __restrict__ y){
    int i = blockIdx.x*blockDim.x + threadIdx.x;
    if (i < NTOT){
        float a = x[3*i+0], b = x[3*i+1], c = x[3*i+2];
        g_PX[i] = make_float4(a, b, c, 0.5f*(a*a + b*b + c*c));
        a = y[3*i+0]; b = y[3*i+1]; c = y[3*i+2];
        g_PY[i] = make_float4(a, b, c, 0.5f*(a*a + b*b + c*c));
    }
}

// One launch = one annealing stage: 4 softmin tasks x 2 batches x 512 row-blocks.
// task 0: a_y' = softmin(eps, C_yx, a_log + b_x/eps)   P=y, Q=x, dual=b_x
// task 1: b_x' = softmin(eps, C_xy, b_log + a_y/eps)   P=x, Q=y, dual=a_y
// task 2: a_x' = softmin(eps, C_xx, a_log + a_x/eps)   P=x, Q=x, dual=a_x
// task 3: b_y' = softmin(eps, C_yy, b_log + b_y/eps)   P=y, Q=y, dual=b_y
// mode 0: init (no dual term); mode 1: 0.5*(old+new); mode 2: plain store.
__global__ __launch_bounds__(256, 2)
void softmin_kernel(float eps, int src, int dst, int mode)
{
    __shared__ float sqx[HALF_J], sqy[HALF_J], sqz[HALF_J], stj[HALF_J];
    __shared__ float sred[8][8];
    __shared__ float sbro[8];

    const int tid    = threadIdx.x;
    const int rowblk = blockIdx.x & 511;     // 512 row-blocks of 8 rows
    const int combo  = blockIdx.x >> 9;      // 0..7
    const int task   = combo >> 1;
    const int batch  = combo & 1;
    const int base   = batch * NPTS;

    const float s2 = (1.0f / eps) * LOG2E_F; // scale into log2 domain

    const float4* P; const float4* Q; const float* dualin; float* outp; const float* oldp;
    if      (task == 0){ P=g_PY+base; Q=g_PX+base; dualin=g_dual[src][1]+base; outp=g_dual[dst][0]+base; oldp=g_dual[src][0]+base; }
    else if (task == 1){ P=g_PX+base; Q=g_PY+base; dualin=g_dual[src][0]+base; outp=g_dual[dst][1]+base; oldp=g_dual[src][1]+base; }
    else if (task == 2){ P=g_PX+base; Q=g_PX+base; dualin=g_dual[src][2]+base; outp=g_dual[dst][2]+base; oldp=g_dual[src][2]+base; }
    else               { P=g_PY+base; Q=g_PY+base; dualin=g_dual[src][3]+base; outp=g_dual[dst][3]+base; oldp=g_dual[src][3]+base; }

    const int row0 = rowblk * 8;

    // Loop-invariant packed row constants (p scaled into log2 domain).
    // Row additive constant (logw - 0.5|p|^2/eps) folded OUT of the LSE.
    unsigned long long pxx[8], pyy[8], pzz[8];
#pragma unroll
    for (int r = 0; r < 8; r++){
        float4 p = P[row0 + r];
        float a = p.x * s2, b = p.y * s2, c = p.z * s2;
        pxx[r] = pack2(a, a);
        pyy[r] = pack2(b, b);
        pzz[r] = pack2(c, c);
    }

    // Stage one 2048-column half into SoA shared (tj = (dual_j - 0.5|q|^2)*s2)
    auto stage = [&](int h){
        const int jg0 = h * HALF_J;
#pragma unroll
        for (int l = tid; l < HALF_J; l += 256){
            float4 q = Q[jg0 + l];
            float tj = (mode == 0) ? (-q.w * s2) : ((dualin[jg0 + l] - q.w) * s2);
            sqx[l] = q.x; sqy[l] = q.y; sqz[l] = q.z; stj[l] = tj;
        }
    };

    // ---------------- pass 1: row maxima ----------------
    float m_lo[8], m_hi[8];
#pragma unroll
    for (int r = 0; r < 8; r++){ m_lo[r] = -3.0e38f; m_hi[r] = -3.0e38f; }

    auto pass1_half = [&](){
#pragma unroll
        for (int k = 0; k < 4; k++){
            const int l = 2*tid + 512*k;
            unsigned long long qx2 = *(const unsigned long long*)(sqx + l);
            unsigned long long qy2 = *(const unsigned long long*)(sqy + l);
            unsigned long long qz2 = *(const unsigned long long*)(sqz + l);
            unsigned long long tj2 = *(const unsigned long long*)(stj + l);
#pragma unroll
            for (int r = 0; r < 8; r++){
                unsigned long long v2 = ffma2(pxx[r], qx2,
                                        ffma2(pyy[r], qy2,
                                        ffma2(pzz[r], qz2, tj2)));
                float lo, hi; unpack2(v2, lo, hi);
                m_lo[r] = fmaxf(m_lo[r], lo);
                m_hi[r] = fmaxf(m_hi[r], hi);
            }
        }
    };

    stage(0); __syncthreads();
    pass1_half(); __syncthreads();
    stage(1); __syncthreads();
    pass1_half();
    // half 1 remains staged for the first half of pass 2

    // block-reduce the 8 row maxima
#pragma unroll
    for (int r = 0; r < 8; r++){
        float v = fmaxf(m_lo[r], m_hi[r]);
#pragma unroll
        for (int o = 16; o; o >>= 1) v = fmaxf(v, __shfl_xor_sync(0xffffffffu, v, o));
        if ((tid & 31) == 0) sred[tid >> 5][r] = v;
    }
    __syncthreads();
    if (tid < 8){
        float v = sred[0][tid];
#pragma unroll
        for (int w = 1; w < 8; w++) v = fmaxf(v, sred[w][tid]);
        sbro[tid] = v;
    }
    __syncthreads();

    unsigned long long nM2[8];
#pragma unroll
    for (int r = 0; r < 8; r++){
        float nm = -sbro[r];
        nM2[r] = pack2(nm, nm);
    }

    // ---------------- pass 2: sum of exp2(v - M) ----------------
    float s_lo[8], s_hi[8];
#pragma unroll
    for (int r = 0; r < 8; r++){ s_lo[r] = 0.0f; s_hi[r] = 0.0f; }

    auto pass2_half = [&](){
#pragma unroll
        for (int k = 0; k < 4; k++){
            const int l = 2*tid + 512*k;
            unsigned long long qx2 = *(const unsigned long long*)(sqx + l);
            unsigned long long qy2 = *(const unsigned long long*)(sqy + l);
            unsigned long long qz2 = *(const unsigned long long*)(sqz + l);
            unsigned long long tj2 = *(const unsigned long long*)(stj + l);
#pragma unroll
            for (int r = 0; r < 8; r++){
                unsigned long long v2 = ffma2(pxx[r], qx2,
                                        ffma2(pyy[r], qy2,
                                        ffma2(pzz[r], qz2, tj2)));
                unsigned long long w2 = fadd2(v2, nM2[r]);
                float lo, hi; unpack2(w2, lo, hi);
                s_lo[r] += ex2f(lo);
                s_hi[r] += ex2f(hi);
            }
        }
    };

    pass2_half();            // half 1 (already staged)
    __syncthreads();
    stage(0); __syncthreads();
    pass2_half();            // half 0

    // block-reduce the 8 row sums and write results
#pragma unroll
    for (int r = 0; r < 8; r++){
        float v = s_lo[r] + s_hi[r];
#pragma unroll
        for (int o = 16; o; o >>= 1) v += __shfl_xor_sync(0xffffffffu, v, o);
        if ((tid & 31) == 0) sred[tid >> 5][r] = v;
    }
    __syncthreads();
    if (tid < 8){
        float v = 0.0f;
#pragma unroll
        for (int w = 0; w < 8; w++) v += sred[w][tid];
        float4 p  = P[row0 + tid];
        float rbv = LOGW_F * LOG2E_F - p.w * s2;   // (logw - 0.5|p|^2/eps)*log2e
        float res = -(eps * LN2_F) * (rbv + sbro[tid] + lg2f(v));
        int row = row0 + tid;
        if (mode == 1) res = 0.5f * (oldp[row] + res);
        outp[row] = res;
    }
}

// F = sum_b [ mean_i(b_x - a_x) + mean_j(a_y - b_y) ]
__global__ void finalize_kernel(int buf, float* __restrict__ out)
{
    const int tid = threadIdx.x;
    const float* ay = g_dual[buf][0];
    const float* bx = g_dual[buf][1];
    const float* ax = g_dual[buf][2];
    const float* by = g_dual[buf][3];
    double acc = 0.0;
    for (int i = tid; i < NTOT; i += 256){
        acc += (double)bx[i] - (double)ax[i];
        acc += (double)ay[i] - (double)by[i];
    }
    __shared__ double sd[8];
#pragma unroll
    for (int o = 16; o; o >>= 1) acc += __shfl_xor_sync(0xffffffffu, acc, o);
    if ((tid & 31) == 0) sd[tid >> 5] = acc;
    __syncthreads();
    if (tid == 0){
        double t = 0.0;
        for (int w = 0; w < 8; w++) t += sd[w];
        out[0] = (float)(t / 4096.0);
    }
}

extern "C" void kernel_launch(void* const* d_in, const int* in_sizes, int n_in,
                              void* d_out, int out_size)
{
    const float* x = (const float*)d_in[0];   // true_data
    const float* y = (const float*)d_in[1];   // particles
    float* out = (float*)d_out;

    pack_kernel<<<(NTOT + 255)/256, 256>>>(x, y);

    // geomloss eps schedule: [16] + exp(arange(2ln4, 2ln0.05, 2ln0.5)) + [0.0025]
    const float epsl[9] = {16.0f, 16.0f, 4.0f, 1.0f, 0.25f,
                           0.0625f, 0.015625f, 0.00390625f, 0.0025f};

    // init stage (eps = 16, no dual term) -> buffer 0
    softmin_kernel<<<4096, 256>>>(16.0f, 0, 0, 0);
    int cur = 0;
    // 9 symmetrized eps-scaling iterations (averaged updates, double buffered)
    for (int i = 0; i < 9; i++){
        softmin_kernel<<<4096, 256>>>(epsl[i], cur, cur ^ 1, 1);
        cur ^= 1;
    }
    // final extrapolation at eps = blur^2
    softmin_kernel<<<4096, 256>>>(0.0025f, cur, cur ^ 1, 2);
    cur ^= 1;

    finalize_kernel<<<1, 256>>>(cur, out);
}

// round 9
// speedup vs baseline: 1.2546x; 1.2546x over previous
#include <cuda_runtime.h>

#define BATCH 2
#define NPTS  4096
#define NTOT  (BATCH*NPTS)

#define LOG2E_F 1.4426950408889634f
#define LN2_F   0.6931471805599453f
#define LOGW_F  (-8.317766166719343f)   /* -ln(4096), uniform weights both sides */

typedef unsigned long long u64;

// Packed point data: (x, y, z, 0.5*|p|^2). side 0 = true_data (x), side 1 = particles (y)
__device__ float4 g_PX[NTOT];
__device__ float4 g_PY[NTOT];
// SoA column geometry per side, 16B aligned for LDG.64 pair loads
__device__ __align__(16) float g_qx[2][NTOT];
__device__ __align__(16) float g_qy[2][NTOT];
__device__ __align__(16) float g_qz[2][NTOT];
// Per-task precomputed column term tj = (dual_j - 0.5|q_j|^2) * log2e/eps, double-buffered
__device__ __align__(16) float g_tj[2][4][NTOT];
// Dual potentials, double-buffered: which: 0=a_y, 1=b_x, 2=a_x, 3=b_y
__device__ float g_dual[2][4][NTOT];

// ---- f32x2 packed helpers (sm_103a) ----
__device__ __forceinline__ u64 pack2(float lo, float hi){
    u64 r;
    asm("mov.b64 %0, {%1, %2};" : "=l"(r)
        : "r"(__float_as_uint(lo)), "r"(__float_as_uint(hi)));
    return r;
}
__device__ __forceinline__ void unpack2(u64 v, float &lo, float &hi){
    unsigned int a, b;
    asm("mov.b64 {%0, %1}, %2;" : "=r"(a), "=r"(b) : "l"(v));
    lo = __uint_as_float(a); hi = __uint_as_float(b);
}
__device__ __forceinline__ u64 ffma2(u64 a, u64 b, u64 c){
    u64 d;
    asm("fma.rn.f32x2 %0, %1, %2, %3;" : "=l"(d) : "l"(a), "l"(b), "l"(c));
    return d;
}
__device__ __forceinline__ u64 fadd2(u64 a, u64 b){
    u64 d;
    asm("add.rn.f32x2 %0, %1, %2;" : "=l"(d) : "l"(a), "l"(b));
    return d;
}
__device__ __forceinline__ float ex2f(float x){ float r; asm("ex2.approx.ftz.f32 %0, %1;" : "=f"(r) : "f"(x)); return r; }
__device__ __forceinline__ float lg2f(float x){ float r; asm("lg2.approx.f32 %0, %1;"     : "=f"(r) : "f"(x)); return r; }

// Build packed points, SoA columns, and the tj arrays for the FIRST launch
// (mode 0: tj = -0.5|q|^2 * s2_0, same for both tasks reading that side).
__global__ void pack_kernel(const float* __restrict__ x, const float* __restrict__ y,
                            float s2_0){
    int i = blockIdx.x*blockDim.x + threadIdx.x;
    if (i < NTOT){
        float a = x[3*i+0], b = x[3*i+1], c = x[3*i+2];
        float w = 0.5f*(a*a + b*b + c*c);
        g_PX[i] = make_float4(a, b, c, w);
        g_qx[0][i] = a; g_qy[0][i] = b; g_qz[0][i] = c;
        g_tj[0][0][i] = -w * s2_0;           // task0 columns = X side
        g_tj[0][2][i] = -w * s2_0;           // task2 columns = X side
        a = y[3*i+0]; b = y[3*i+1]; c = y[3*i+2];
        w = 0.5f*(a*a + b*b + c*c);
        g_PY[i] = make_float4(a, b, c, w);
        g_qx[1][i] = a; g_qy[1][i] = b; g_qz[1][i] = c;
        g_tj[0][1][i] = -w * s2_0;           // task1 columns = Y side
        g_tj[0][3][i] = -w * s2_0;           // task3 columns = Y side
    }
}

// One launch = one stage: 4 softmin tasks x 2 batches x 512 row-blocks of 8 rows.
// task 0: a_y' = softmin(C_yx, b_x)  P=Y, cols=X   task 1: b_x' = softmin(C_xy, a_y)  P=X, cols=Y
// task 2: a_x' = softmin(C_xx, a_x)  P=X, cols=X   task 3: b_y' = softmin(C_yy, b_y)  P=Y, cols=Y
// mode 0: plain store (init); mode 1: 0.5*(old+new); mode 2: plain store (final).
// Epilogue also writes NEXT launch's tj array (scaled by s2n) into g_tj[rdbuf^1].
__global__ __launch_bounds__(256, 2)
void softmin_kernel(float eps, float s2n, int src, int dst, int rdbuf, int mode)
{
    __shared__ float sred[8][8];
    __shared__ float sbro[8];

    const int tid    = threadIdx.x;
    const int rowblk = blockIdx.x & 511;     // 512 row-blocks of 8 rows
    const int combo  = blockIdx.x >> 9;      // 0..7
    const int task   = combo >> 1;
    const int batch  = combo & 1;
    const int base   = batch * NPTS;

    const float s2 = (1.0f / eps) * LOG2E_F;

    const int side = (task == 0 || task == 2) ? 0 : 1;   // column side
    const float4* P = (task == 0 || task == 3) ? (g_PY + base) : (g_PX + base);
    const int which = task;                               // dual slot this task writes
    float* outp = g_dual[dst][which] + base;
    const float* oldp = g_dual[src][which] + base;

    const u64* __restrict__ qx2 = (const u64*)(g_qx[side] + base);
    const u64* __restrict__ qy2 = (const u64*)(g_qy[side] + base);
    const u64* __restrict__ qz2 = (const u64*)(g_qz[side] + base);
    const u64* __restrict__ tj2 = (const u64*)(g_tj[rdbuf][task] + base);

    const int row0 = rowblk * 8;

    // Loop-invariant packed row constants (p scaled into log2 domain).
    u64 pxx[8], pyy[8], pzz[8];
#pragma unroll
    for (int r = 0; r < 8; r++){
        float4 p = P[row0 + r];
        float a = p.x * s2, b = p.y * s2, c = p.z * s2;
        pxx[r] = pack2(a, a);
        pyy[r] = pack2(b, b);
        pzz[r] = pack2(c, c);
    }

    // ---------------- pass 1: row maxima ----------------
    float m_lo[8], m_hi[8];
#pragma unroll
    for (int r = 0; r < 8; r++){ m_lo[r] = -3.0e38f; m_hi[r] = -3.0e38f; }

#pragma unroll 2
    for (int k = 0; k < 8; k++){
        const int jp = tid + (k << 8);       // pair index 0..2047
        u64 qxv = qx2[jp], qyv = qy2[jp], qzv = qz2[jp], tjv = tj2[jp];
#pragma unroll
        for (int r = 0; r < 8; r++){
            u64 v2 = ffma2(pxx[r], qxv, ffma2(pyy[r], qyv, ffma2(pzz[r], qzv, tjv)));
            float lo, hi; unpack2(v2, lo, hi);
            m_lo[r] = fmaxf(m_lo[r], lo);
            m_hi[r] = fmaxf(m_hi[r], hi);
        }
    }

#pragma unroll
    for (int r = 0; r < 8; r++){
        float v = fmaxf(m_lo[r], m_hi[r]);
#pragma unroll
        for (int o = 16; o; o >>= 1) v = fmaxf(v, __shfl_xor_sync(0xffffffffu, v, o));
        if ((tid & 31) == 0) sred[tid >> 5][r] = v;
    }
    __syncthreads();
    if (tid < 8){
        float v = sred[0][tid];
#pragma unroll
        for (int w = 1; w < 8; w++) v = fmaxf(v, sred[w][tid]);
        sbro[tid] = v;
    }
    __syncthreads();

    u64 nM2[8];
#pragma unroll
    for (int r = 0; r < 8; r++){
        float nm = -sbro[r];
        nM2[r] = pack2(nm, nm);
    }

    // ---------------- pass 2: sum of exp2(v - M) ----------------
    float s_lo[8], s_hi[8];
#pragma unroll
    for (int r = 0; r < 8; r++){ s_lo[r] = 0.0f; s_hi[r] = 0.0f; }

#pragma unroll 2
    for (int k = 0; k < 8; k++){
        const int jp = tid + (k << 8);
        u64 qxv = qx2[jp], qyv = qy2[jp], qzv = qz2[jp], tjv = tj2[jp];
#pragma unroll
        for (int r = 0; r < 8; r++){
            u64 v2 = ffma2(pxx[r], qxv, ffma2(pyy[r], qyv, ffma2(pzz[r], qzv, tjv)));
            u64 w2 = fadd2(v2, nM2[r]);
            float lo, hi; unpack2(w2, lo, hi);
            s_lo[r] += ex2f(lo);
            s_hi[r] += ex2f(hi);
        }
    }

#pragma unroll
    for (int r = 0; r < 8; r++){
        float v = s_lo[r] + s_hi[r];
#pragma unroll
        for (int o = 16; o; o >>= 1) v += __shfl_xor_sync(0xffffffffu, v, o);
        if ((tid & 31) == 0) sred[tid >> 5][r] = v;
    }
    __syncthreads();
    if (tid < 8){
        float v = 0.0f;
#pragma unroll
        for (int w = 0; w < 8; w++) v += sred[w][tid];
        float4 p  = P[row0 + tid];
        float rbv = LOGW_F * LOG2E_F - p.w * s2;   // (logw - 0.5|p|^2/eps)*log2e
        float res = -(eps * LN2_F) * (rbv + sbro[tid] + lg2f(v));
        int row = row0 + tid;
        if (mode == 1) res = 0.5f * (oldp[row] + res);
        outp[row] = res;
        // Write next launch's tj for the tj-array this task's dual feeds:
        // T[0] <- b_x (task1), T[1] <- a_y (task0), T[2] <- a_x (task2), T[3] <- b_y (task3)
        int tjt = (task == 0) ? 1 : (task == 1) ? 0 : task;
        g_tj[rdbuf ^ 1][tjt][base + row] = (res - p.w) * s2n;
    }
}

// F = sum_b [ mean_i(b_x - a_x) + mean_j(a_y - b_y) ]
__global__ void finalize_kernel(int buf, float* __restrict__ out)
{
    const int tid = threadIdx.x;
    const float* ay = g_dual[buf][0];
    const float* bx = g_dual[buf][1];
    const float* ax = g_dual[buf][2];
    const float* by = g_dual[buf][3];
    double acc = 0.0;
    for (int i = tid; i < NTOT; i += 256){
        acc += (double)bx[i] - (double)ax[i];
        acc += (double)ay[i] - (double)by[i];
    }
    __shared__ double sd[8];
#pragma unroll
    for (int o = 16; o; o >>= 1) acc += __shfl_xor_sync(0xffffffffu, acc, o);
    if ((tid & 31) == 0) sd[tid >> 5] = acc;
    __syncthreads();
    if (tid == 0){
        double t = 0.0;
        for (int w = 0; w < 8; w++) t += sd[w];
        out[0] = (float)(t / 4096.0);
    }
}

extern "C" void kernel_launch(void* const* d_in, const int* in_sizes, int n_in,
                              void* d_out, int out_size)
{
    const float* x = (const float*)d_in[0];   // true_data
    const float* y = (const float*)d_in[1];   // particles
    float* out = (float*)d_out;

    // Launch eps sequence: init(16), 9 annealing steps, final extrapolation(0.0025)
    const float E[11] = {16.0f,
                         16.0f, 16.0f, 4.0f, 1.0f, 0.25f,
                         0.0625f, 0.015625f, 0.00390625f, 0.0025f,
                         0.0025f};

    pack_kernel<<<(NTOT + 255)/256, 256>>>(x, y, LOG2E_F / E[0]);

    int cur = 0, rb = 0;
    // L0: init (mode 0) -> dual buffer 0; writes tj for L1 (eps E[1])
    softmin_kernel<<<4096, 256>>>(E[0], LOG2E_F / E[1], 0, 0, rb, 0);
    rb ^= 1;
    // L1..L9: annealing (mode 1, averaged, double-buffered duals)
    for (int i = 1; i <= 9; i++){
        softmin_kernel<<<4096, 256>>>(E[i], LOG2E_F / E[i + 1], cur, cur ^ 1, rb, 1);
        cur ^= 1; rb ^= 1;
    }
    // L10: final extrapolation (mode 2)
    softmin_kernel<<<4096, 256>>>(E[10], LOG2E_F / E[10], cur, cur ^ 1, rb, 2);
    cur ^= 1;

    finalize_kernel<<<1, 256>>>(cur, out);
}

// round 12
// speedup vs baseline: 1.2867x; 1.0256x over previous
#include <cuda_runtime.h>

#define BATCH 2
#define NPTS  4096
#define NTOT  (BATCH*NPTS)

#define LOG2E_F 1.4426950408889634f
#define LN2_F   0.6931471805599453f
#define LOGW_F  (-8.317766166719343f)   /* -ln(4096), uniform weights both sides */

typedef unsigned long long u64;

// Packed point data: (x, y, z, 0.5*|p|^2). side 0 = true_data (x), side 1 = particles (y)
__device__ float4 g_PX[NTOT];
__device__ float4 g_PY[NTOT];
// SoA column geometry per side, 16B aligned for LDG.64 pair loads
__device__ __align__(16) float g_qx[2][NTOT];
__device__ __align__(16) float g_qy[2][NTOT];
__device__ __align__(16) float g_qz[2][NTOT];
// Per-task precomputed column term tj = (dual_j - 0.5|q_j|^2) * log2e/eps, double-buffered
__device__ __align__(16) float g_tj[2][4][NTOT];
// Dual potentials, double-buffered: which: 0=a_y, 1=b_x, 2=a_x, 3=b_y
__device__ float g_dual[2][4][NTOT];
// finalize partials
__device__ double g_part[16];

// ---- f32x2 packed helpers (sm_103a) ----
__device__ __forceinline__ u64 pack2(float lo, float hi){
    u64 r;
    asm("mov.b64 %0, {%1, %2};" : "=l"(r)
        : "r"(__float_as_uint(lo)), "r"(__float_as_uint(hi)));
    return r;
}
__device__ __forceinline__ void unpack2(u64 v, float &lo, float &hi){
    unsigned int a, b;
    asm("mov.b64 {%0, %1}, %2;" : "=r"(a), "=r"(b) : "l"(v));
    lo = __uint_as_float(a); hi = __uint_as_float(b);
}
__device__ __forceinline__ u64 ffma2(u64 a, u64 b, u64 c){
    u64 d;
    asm("fma.rn.f32x2 %0, %1, %2, %3;" : "=l"(d) : "l"(a), "l"(b), "l"(c));
    return d;
}
__device__ __forceinline__ u64 fadd2(u64 a, u64 b){
    u64 d;
    asm("add.rn.f32x2 %0, %1, %2;" : "=l"(d) : "l"(a), "l"(b));
    return d;
}
__device__ __forceinline__ float ex2f(float x){ float r; asm("ex2.approx.ftz.f32 %0, %1;" : "=f"(r) : "f"(x)); return r; }
__device__ __forceinline__ float lg2f(float x){ float r; asm("lg2.approx.f32 %0, %1;"     : "=f"(r) : "f"(x)); return r; }

// Build packed points, SoA columns, and the tj arrays for the FIRST launch
__global__ void pack_kernel(const float* __restrict__ x, const float* __restrict__ y,
                            float s2_0){
    int i = blockIdx.x*blockDim.x + threadIdx.x;
    if (i < NTOT){
        float a = x[3*i+0], b = x[3*i+1], c = x[3*i+2];
        float w = 0.5f*(a*a + b*b + c*c);
        g_PX[i] = make_float4(a, b, c, w);
        g_qx[0][i] = a; g_qy[0][i] = b; g_qz[0][i] = c;
        g_tj[0][0][i] = -w * s2_0;           // task0 columns = X side
        g_tj[0][2][i] = -w * s2_0;           // task2 columns = X side
        a = y[3*i+0]; b = y[3*i+1]; c = y[3*i+2];
        w = 0.5f*(a*a + b*b + c*c);
        g_PY[i] = make_float4(a, b, c, w);
        g_qx[1][i] = a; g_qy[1][i] = b; g_qz[1][i] = c;
        g_tj[0][1][i] = -w * s2_0;           // task1 columns = Y side
        g_tj[0][3][i] = -w * s2_0;           // task3 columns = Y side
    }
}

// One launch = one stage: 4 softmin tasks x 2 batches x 512 row-blocks of 8 rows.
// task 0: a_y' (P=Y, cols=X)  task 1: b_x' (P=X, cols=Y)
// task 2: a_x' (P=X, cols=X)  task 3: b_y' (P=Y, cols=Y)
// mode 0: plain store (init); mode 1: 0.5*(old+new); mode 2: plain store (final).
// Epilogue writes NEXT launch's tj (scaled by s2n) into g_tj[rdbuf^1].
__global__ __launch_bounds__(256, 2)
void softmin_kernel(float eps, float s2n, int src, int dst, int rdbuf, int mode)
{
    __shared__ float sred[8][8];
    __shared__ float sbro[8];

    const int tid    = threadIdx.x;
    const int rowblk = blockIdx.x & 511;     // 512 row-blocks of 8 rows
    const int combo  = blockIdx.x >> 9;      // 0..7
    const int task   = combo >> 1;
    const int batch  = combo & 1;
    const int base   = batch * NPTS;

    const float s2 = (1.0f / eps) * LOG2E_F;

    const int side = (task == 0 || task == 2) ? 0 : 1;   // column side
    const float4* P = (task == 0 || task == 3) ? (g_PY + base) : (g_PX + base);
    const int which = task;                               // dual slot this task writes
    float* outp = g_dual[dst][which] + base;
    const float* oldp = g_dual[src][which] + base;

    const u64* __restrict__ qx2 = (const u64*)(g_qx[side] + base) + tid;
    const u64* __restrict__ qy2 = (const u64*)(g_qy[side] + base) + tid;
    const u64* __restrict__ qz2 = (const u64*)(g_qz[side] + base) + tid;
    const u64* __restrict__ tj2 = (const u64*)(g_tj[rdbuf][task] + base) + tid;

    const int row0 = rowblk * 8;

    // Loop-invariant packed row constants (p scaled into log2 domain).
    u64 pxx[8], pyy[8], pzz[8];
#pragma unroll
    for (int r = 0; r < 8; r++){
        float4 p = P[row0 + r];
        float a = p.x * s2, b = p.y * s2, c = p.z * s2;
        pxx[r] = pack2(a, a);
        pyy[r] = pack2(b, b);
        pzz[r] = pack2(c, c);
    }

    // ---------------- pass 1: row maxima ----------------
    float m_lo[8], m_hi[8];
#pragma unroll
    for (int r = 0; r < 8; r++){ m_lo[r] = -3.0e38f; m_hi[r] = -3.0e38f; }

#pragma unroll
    for (int k = 0; k < 8; k++){
        u64 qxv = qx2[k << 8], qyv = qy2[k << 8], qzv = qz2[k << 8], tjv = tj2[k << 8];
#pragma unroll
        for (int r = 0; r < 8; r++){
            u64 v2 = ffma2(pxx[r], qxv, ffma2(pyy[r], qyv, ffma2(pzz[r], qzv, tjv)));
            float lo, hi; unpack2(v2, lo, hi);
            m_lo[r] = fmaxf(m_lo[r], lo);
            m_hi[r] = fmaxf(m_hi[r], hi);
        }
    }

#pragma unroll
    for (int r = 0; r < 8; r++){
        float v = fmaxf(m_lo[r], m_hi[r]);
#pragma unroll
        for (int o = 16; o; o >>= 1) v = fmaxf(v, __shfl_xor_sync(0xffffffffu, v, o));
        if ((tid & 31) == 0) sred[tid >> 5][r] = v;
    }
    __syncthreads();
    if (tid < 8){
        float v = sred[0][tid];
#pragma unroll
        for (int w = 1; w < 8; w++) v = fmaxf(v, sred[w][tid]);
        sbro[tid] = v;
    }
    __syncthreads();

    u64 nM2[8];
#pragma unroll
    for (int r = 0; r < 8; r++){
        float nm = -sbro[r];
        nM2[r] = pack2(nm, nm);
    }

    // ---------------- pass 2: sum of exp2(v - M), packed accumulation ----------------
    u64 sacc[8];
#pragma unroll
    for (int r = 0; r < 8; r++) sacc[r] = 0ull;

#pragma unroll
    for (int k = 0; k < 8; k++){
        u64 qxv = qx2[k << 8], qyv = qy2[k << 8], qzv = qz2[k << 8], tjv = tj2[k << 8];
#pragma unroll
        for (int r = 0; r < 8; r++){
            u64 v2 = ffma2(pxx[r], qxv, ffma2(pyy[r], qyv, ffma2(pzz[r], qzv, tjv)));
            u64 w2 = fadd2(v2, nM2[r]);
            float lo, hi; unpack2(w2, lo, hi);
            float elo = ex2f(lo);
            float ehi = ex2f(hi);
            sacc[r] = fadd2(sacc[r], pack2(elo, ehi));   // pack2 = register pairing
        }
    }

#pragma unroll
    for (int r = 0; r < 8; r++){
        float lo, hi; unpack2(sacc[r], lo, hi);
        float v = lo + hi;
#pragma unroll
        for (int o = 16; o; o >>= 1) v += __shfl_xor_sync(0xffffffffu, v, o);
        if ((tid & 31) == 0) sred[tid >> 5][r] = v;
    }
    __syncthreads();
    if (tid < 8){
        float v = 0.0f;
#pragma unroll
        for (int w = 0; w < 8; w++) v += sred[w][tid];
        float4 p  = P[row0 + tid];
        float rbv = LOGW_F * LOG2E_F - p.w * s2;   // (logw - 0.5|p|^2/eps)*log2e
        float res = -(eps * LN2_F) * (rbv + sbro[tid] + lg2f(v));
        int row = row0 + tid;
        if (mode == 1) res = 0.5f * (oldp[row] + res);
        outp[row] = res;
        // Next launch's tj for the tj-array this task's dual feeds:
        // T[0] <- b_x (task1), T[1] <- a_y (task0), T[2] <- a_x (task2), T[3] <- b_y (task3)
        int tjt = (task == 0) ? 1 : (task == 1) ? 0 : task;
        g_tj[rdbuf ^ 1][tjt][base + row] = (res - p.w) * s2n;
    }
}

// F = sum_b [ mean_i(b_x - a_x) + mean_j(a_y - b_y) ] — 16-block partials
__global__ void finalize_part(int buf)
{
    const int tid = threadIdx.x;
    const int blk = blockIdx.x;                 // 0..15
    const float* ay = g_dual[buf][0];
    const float* bx = g_dual[buf][1];
    const float* ax = g_dual[buf][2];
    const float* by = g_dual[buf][3];
    double acc = 0.0;
    const int i0 = blk * (NTOT / 16);
#pragma unroll 2
    for (int t = tid; t < NTOT / 16; t += 256){
        int i = i0 + t;
        acc += (double)bx[i] - (double)ax[i];
        acc += (double)ay[i] - (double)by[i];
    }
    __shared__ double sd[8];
#pragma unroll
    for (int o = 16; o; o >>= 1) acc += __shfl_xor_sync(0xffffffffu, acc, o);
    if ((tid & 31) == 0) sd[tid >> 5] = acc;
    __syncthreads();
    if (tid == 0){
        double t = 0.0;
        for (int w = 0; w < 8; w++) t += sd[w];
        g_part[blk] = t;
    }
}

__global__ void finalize_sum(float* __restrict__ out)
{
    if (threadIdx.x == 0){
        double t = 0.0;
        for (int b = 0; b < 16; b++) t += g_part[b];
        out[0] = (float)(t / 4096.0);
    }
}

extern "C" void kernel_launch(void* const* d_in, const int* in_sizes, int n_in,
                              void* d_out, int out_size)
{
    const float* x = (const float*)d_in[0];   // true_data
    const float* y = (const float*)d_in[1];   // particles
    float* out = (float*)d_out;

    // Launch eps sequence: init(16), 9 annealing steps, final extrapolation(0.0025)
    const float E[11] = {16.0f,
                         16.0f, 16.0f, 4.0f, 1.0f, 0.25f,
                         0.0625f, 0.015625f, 0.00390625f, 0.0025f,
                         0.0025f};

    pack_kernel<<<(NTOT + 255)/256, 256>>>(x, y, LOG2E_F / E[0]);

    int cur = 0, rb = 0;
    // L0: init (mode 0) -> dual buffer 0; writes tj for L1 (eps E[1])
    softmin_kernel<<<4096, 256>>>(E[0], LOG2E_F / E[1], 0, 0, rb, 0);
    rb ^= 1;
    // L1..L9: annealing (mode 1, averaged, double-buffered duals)
    for (int i = 1; i <= 9; i++){
        softmin_kernel<<<4096, 256>>>(E[i], LOG2E_F / E[i + 1], cur, cur ^ 1, rb, 1);
        cur ^= 1; rb ^= 1;
    }
    // L10: final extrapolation (mode 2)
    softmin_kernel<<<4096, 256>>>(E[10], LOG2E_F / E[10], cur, cur ^ 1, rb, 2);
    cur ^= 1;

    finalize_part<<<16, 256>>>(cur);
    finalize_sum<<<1, 32>>>(out);
}